// round 4
// baseline (speedup 1.0000x reference)
#include <cuda_runtime.h>
#include <cuda_bf16.h>
#include <math.h>

#define B 64
#define S 4096
#define D 1024
#define NSPLIT 16
#define SPS (S / NSPLIT)   // 256
#define TILE 8
#define NTILE (SPS / TILE) // 32

// ---------------- scratch (device globals: no allocation allowed) ----------
__device__ float g_q[B * D];                 // 256 KB  q = query @ W_align^T
__device__ float g_scores[B * S];            // 1 MB    masked raw scores
__device__ float g_pm[B * NSPLIT];           // per-split running max
__device__ float g_pl[B * NSPLIT];           // per-split running sum
__device__ float g_pacc[B * NSPLIT * D];     // 4 MB    per-split unnormalized acc
__device__ float g_wc[B * D];                // weight_context
__device__ float g_lin[B * D];               // pre-tanh accumulator

// ---------------- zero init for atomic accumulators ------------------------
__global__ void zero_kernel() {
    int i = blockIdx.x * blockDim.x + threadIdx.x;   // 64*256 = 16384 float4 per array
    float4 z = make_float4(0.f, 0.f, 0.f, 0.f);
    reinterpret_cast<float4*>(g_q)[i] = z;
    reinterpret_cast<float4*>(g_lin)[i] = z;
}

// ---------------- small skinny GEMM: out[b,d] += sum_k A[b,k] * W[d,k] -----
// grid.x = D/32 d-tiles; grid.y = 2*KS: (y>>3)=operand pair, (y&7)=k-split of 128
#define BN 32
#define BK 32
#define KS 8
#define KCHUNK (D / KS)    // 128

__global__ void __launch_bounds__(256) gemm_nt(
    const float* __restrict__ A0, const float* __restrict__ W0,
    const float* __restrict__ A1, const float* __restrict__ W1,
    float* __restrict__ out)
{
    const int which = blockIdx.y >> 3;
    const float* __restrict__ A = which ? A1 : A0;
    const float* __restrict__ W = which ? W1 : W0;
    const int k0  = (blockIdx.y & (KS - 1)) * KCHUNK;
    const int dn0 = blockIdx.x * BN;

    __shared__ float As[64][BK + 1];
    __shared__ float Ws[BN][BK + 1];

    const int tid = threadIdx.x;
    const int tx = tid & 15;   // d pair
    const int ty = tid >> 4;   // b quad
    float acc[4][2] = {};

    for (int bk = 0; bk < KCHUNK; bk += BK) {
        #pragma unroll
        for (int r = 0; r < 2; r++) {
            int idx = tid + r * 256;
            int bb = idx >> 3, kk4 = idx & 7;
            float4 v = *reinterpret_cast<const float4*>(A + bb * D + k0 + bk + kk4 * 4);
            As[bb][kk4 * 4 + 0] = v.x; As[bb][kk4 * 4 + 1] = v.y;
            As[bb][kk4 * 4 + 2] = v.z; As[bb][kk4 * 4 + 3] = v.w;
        }
        {
            int dd = tid >> 3, kk4 = tid & 7;
            float4 v = *reinterpret_cast<const float4*>(W + (size_t)(dn0 + dd) * D + k0 + bk + kk4 * 4);
            Ws[dd][kk4 * 4 + 0] = v.x; Ws[dd][kk4 * 4 + 1] = v.y;
            Ws[dd][kk4 * 4 + 2] = v.z; Ws[dd][kk4 * 4 + 3] = v.w;
        }
        __syncthreads();
        #pragma unroll
        for (int kk = 0; kk < BK; kk++) {
            float w0 = Ws[tx * 2][kk];
            float w1 = Ws[tx * 2 + 1][kk];
            #pragma unroll
            for (int i = 0; i < 4; i++) {
                float a = As[ty * 4 + i][kk];
                acc[i][0] = fmaf(a, w0, acc[i][0]);
                acc[i][1] = fmaf(a, w1, acc[i][1]);
            }
        }
        __syncthreads();
    }
    #pragma unroll
    for (int i = 0; i < 4; i++) {
        int b = ty * 4 + i;
        atomicAdd(&out[b * D + dn0 + tx * 2 + 0], acc[i][0]);
        atomicAdd(&out[b * D + dn0 + tx * 2 + 1], acc[i][1]);
    }
}

// ---------------- flash pass over context (the 1 GiB read) -----------------
// grid = (NSPLIT, B) = 1024 half-size CTAs for load balance (~6.9 per SM,
// ragged by one half-CTA -> ~98% utilization vs 86.5% at 512 CTAs).
// Thread t owns output columns [4t, 4t+4). Context tile is TRANSIENT in
// registers: loaded for the dot, discarded, then re-loaded for the weighted
// accumulate (second read hits L1: 32KB/CTA x 4 CTAs = 128KB < 228KB L1).
__global__ void __launch_bounds__(256, 4) attn_flash(
    const float* __restrict__ ctx, const int* __restrict__ mask)
{
    const int split = blockIdx.x;
    const int b     = blockIdx.y;
    const int tid   = threadIdx.x;
    const int lane  = tid & 31;
    const int wid   = tid >> 5;

    __shared__ float sh_red[2][8][8];    // [parity][row][warp]

    const float4 qr = *reinterpret_cast<const float4*>(g_q + b * D + tid * 4);

    float acc0 = 0.f, acc1 = 0.f, acc2 = 0.f, acc3 = 0.f;
    float m_run = -1e30f, l_run = 0.f;

    const float* __restrict__ cbase = ctx + (size_t)b * S * D + (size_t)split * SPS * D + tid * 4;
    const int*   __restrict__ mbase = mask + b * S + split * SPS;
    const int    sgbase = b * S + split * SPS;

    const bool h16 = (lane & 16) != 0;
    const bool h8  = (lane & 8)  != 0;
    const bool h4  = (lane & 4)  != 0;
    const int  myrow = lane & 7;

    for (int t = 0; t < NTILE; t++) {
        const int s0 = t * TILE;
        const float* tb = cbase + (size_t)s0 * D;
        const int par = t & 1;

        // ---- dot pass: f transient ----
        float p[TILE];
        #pragma unroll
        for (int j = 0; j < TILE; j++) {
            float4 f = *reinterpret_cast<const float4*>(tb + (size_t)j * D);
            p[j] = fmaf(f.x, qr.x, fmaf(f.y, qr.y, fmaf(f.z, qr.z, f.w * qr.w)));
        }

        // ---- butterfly fold: 8 rows x 32 lanes -> row (lane>>2) ----
        #pragma unroll
        for (int j = 0; j < 4; j++) {
            float send = h16 ? p[j] : p[j + 4];
            float recv = __shfl_xor_sync(0xffffffffu, send, 16);
            p[j] = (h16 ? p[j + 4] : p[j]) + recv;
        }
        #pragma unroll
        for (int j = 0; j < 2; j++) {
            float send = h8 ? p[j] : p[j + 2];
            float recv = __shfl_xor_sync(0xffffffffu, send, 8);
            p[j] = (h8 ? p[j + 2] : p[j]) + recv;
        }
        float pr;
        {
            float send = h4 ? p[0] : p[1];
            float recv = __shfl_xor_sync(0xffffffffu, send, 4);
            pr = (h4 ? p[1] : p[0]) + recv;
        }
        pr += __shfl_xor_sync(0xffffffffu, pr, 2);
        pr += __shfl_xor_sync(0xffffffffu, pr, 1);
        if ((lane & 3) == 0) sh_red[par][lane >> 2][wid] = pr;

        __syncthreads();   // single barrier per tile (smem double-buffered)

        // ---- cross-warp combine (redundant per warp) + mask ----
        float v = 0.f;
        #pragma unroll
        for (int w = 0; w < 8; w++) v += sh_red[par][myrow][w];
        float a = (mbase[s0 + myrow] != 0) ? v : -1e30f;
        if (wid == 0 && lane < 8) g_scores[sgbase + s0 + lane] = a;

        float aj[TILE];
        #pragma unroll
        for (int j = 0; j < TILE; j++)
            aj[j] = __shfl_sync(0xffffffffu, a, j, 8);

        // ---- online softmax ----
        float new_m = m_run;
        #pragma unroll
        for (int j = 0; j < TILE; j++) new_m = fmaxf(new_m, aj[j]);
        float scale = __expf(m_run - new_m);
        float wj[TILE];
        float wsum = 0.f;
        #pragma unroll
        for (int j = 0; j < TILE; j++) {
            wj[j] = (aj[j] > -1e29f) ? __expf(aj[j] - new_m) : 0.f;
            wsum += wj[j];
        }
        m_run = new_m;
        l_run = fmaf(l_run, scale, wsum);
        acc0 *= scale; acc1 *= scale; acc2 *= scale; acc3 *= scale;

        // ---- weighted accumulate: re-load tile (L1 hit) ----
        #pragma unroll
        for (int j = 0; j < TILE; j++) {
            float4 f = *reinterpret_cast<const float4*>(tb + (size_t)j * D);
            acc0 = fmaf(wj[j], f.x, acc0);
            acc1 = fmaf(wj[j], f.y, acc1);
            acc2 = fmaf(wj[j], f.z, acc2);
            acc3 = fmaf(wj[j], f.w, acc3);
        }
    }

    if (tid == 0) {
        g_pm[b * NSPLIT + split] = m_run;
        g_pl[b * NSPLIT + split] = l_run;
    }
    float* pa = g_pacc + (size_t)(b * NSPLIT + split) * D + tid * 4;
    pa[0] = acc0; pa[1] = acc1; pa[2] = acc2; pa[3] = acc3;
}

// ---------------- combine splits, normalize attention, emit weight_context -
// grid (B, 4), 256 threads, all float4.
__global__ void __launch_bounds__(256) combine_kernel(float* __restrict__ out_att,
                                                      float* __restrict__ out_wc)
{
    const int b = blockIdx.x;
    const int c = blockIdx.y;
    const int tid = threadIdx.x;

    // pass 1: M
    float M = -1e30f;
    #pragma unroll
    for (int i = 0; i < NSPLIT; i++) M = fmaxf(M, g_pm[b * NSPLIT + i]);
    // pass 2: fac + L (fac only kept live)
    float fac[NSPLIT];
    float L = 0.f;
    #pragma unroll
    for (int i = 0; i < NSPLIT; i++) {
        fac[i] = __expf(g_pm[b * NSPLIT + i] - M);
        L = fmaf(g_pl[b * NSPLIT + i], fac[i], L);
    }
    const float invL = 1.f / L;

    // weight_context: 256 cols (64 float4) per block, threads 0..63
    if (tid < 64) {
        const int d4 = c * 64 + tid;               // float4 index within row
        const float4* pacc4 = reinterpret_cast<const float4*>(g_pacc) + (size_t)b * NSPLIT * (D / 4) + d4;
        float4 acc = make_float4(0.f, 0.f, 0.f, 0.f);
        #pragma unroll
        for (int i = 0; i < NSPLIT; i++) {
            float4 v = pacc4[(size_t)i * (D / 4)];
            acc.x = fmaf(fac[i], v.x, acc.x);
            acc.y = fmaf(fac[i], v.y, acc.y);
            acc.z = fmaf(fac[i], v.z, acc.z);
            acc.w = fmaf(fac[i], v.w, acc.w);
        }
        float4 wc = make_float4(acc.x * invL, acc.y * invL, acc.z * invL, acc.w * invL);
        reinterpret_cast<float4*>(g_wc)[b * (D / 4) + d4] = wc;
        reinterpret_cast<float4*>(out_wc)[b * (D / 4) + d4] = wc;
    }

    // attention: 1024 scores (256 float4) per block, one float4 per thread
    {
        const int s4 = c * 256 + tid;
        float4 sc = reinterpret_cast<const float4*>(g_scores)[b * (S / 4) + s4];
        float4 r = make_float4(__expf(sc.x - M) * invL, __expf(sc.y - M) * invL,
                               __expf(sc.z - M) * invL, __expf(sc.w - M) * invL);
        reinterpret_cast<float4*>(out_att)[b * (S / 4) + s4] = r;
    }
}

// ---------------- tanh epilogue --------------------------------------------
__global__ void tanh_kernel(float* __restrict__ out) {
    int i = (blockIdx.x * blockDim.x + threadIdx.x) * 4;
    float4 v = *reinterpret_cast<const float4*>(g_lin + i);
    float4 r = make_float4(tanhf(v.x), tanhf(v.y), tanhf(v.z), tanhf(v.w));
    *reinterpret_cast<float4*>(out + i) = r;
}

// ---------------- launcher --------------------------------------------------
extern "C" void kernel_launch(void* const* d_in, const int* in_sizes, int n_in,
                              void* d_out, int out_size)
{
    const float* query     = (const float*)d_in[0];   // [B, D]
    const float* context   = (const float*)d_in[1];   // [B, S, D]
    const int*   ctx_mask  = (const int*)  d_in[2];   // [B, S]
    const float* W_align   = (const float*)d_in[3];   // [D, D]
    const float* W_context = (const float*)d_in[4];   // [D, D]
    const float* W_query   = (const float*)d_in[5];   // [D, D]

    float* out  = (float*)d_out;                      // [B, D]
    float* att  = out + B * D;                        // [B, S]
    float* owc  = att + B * S;                        // [B, D]

    // Device addresses of symbols passed as kernel arguments.
    float *pq = nullptr, *plin = nullptr, *pwc = nullptr;
    cudaGetSymbolAddress((void**)&pq,   g_q);
    cudaGetSymbolAddress((void**)&plin, g_lin);
    cudaGetSymbolAddress((void**)&pwc,  g_wc);

    // 1. zero atomic accumulators
    zero_kernel<<<64, 256>>>();

    // 2. q = query @ W_align^T   (split-K x8)
    gemm_nt<<<dim3(D / BN, KS), 256>>>(query, W_align, query, W_align, pq);

    // 3. flash pass over context (1 GiB, read once from DRAM)
    attn_flash<<<dim3(NSPLIT, B), 256>>>(context, ctx_mask);

    // 4. combine splits -> attention + weight_context
    combine_kernel<<<dim3(B, 4), 256>>>(att, owc);

    // 5. g_lin = wc @ W_context^T + query @ W_query^T  (2 operands x 8 k-splits)
    gemm_nt<<<dim3(D / BN, 2 * KS), 256>>>(pwc, W_context, query, W_query, plin);

    // 6. out = tanh(g_lin)
    tanh_kernel<<<64, 256>>>(out);
}

// round 5
// speedup vs baseline: 1.0018x; 1.0018x over previous
#include <cuda_runtime.h>
#include <cuda_bf16.h>
#include <math.h>

#define B 64
#define S 4096
#define D 1024
#define NSPLIT 8
#define SPS (S / NSPLIT)   // 512
#define TILE 8
#define NTILE (SPS / TILE) // 64

#define KS 8               // split-K factor for skinny GEMMs
#define KCHUNK (D / KS)    // 128

// ---------------- scratch (device globals: no allocation allowed) ----------
__device__ float g_qpart[KS * B * D];        // 2 MB  q-projection split-K partials
__device__ float g_scores[B * S];            // 1 MB  masked raw scores
__device__ float g_pm[B * NSPLIT];           // per-split running max
__device__ float g_pl[B * NSPLIT];           // per-split running sum
__device__ float g_pacc[B * NSPLIT * D];     // 2 MB  per-split unnormalized acc
__device__ float g_wc[B * D];                // weight_context
__device__ float g_linpart[2 * KS * B * D];  // 4 MB  output-GEMM partials

// ---------------- small skinny GEMM: partial[y] = A @ W^T over k-chunk -----
// grid.x = D/32 d-tiles; grid.y = #splits: (y>>3)=operand pair, (y&7)=k-chunk
// Plain stores to per-split partial buffers: no atomics, no pre-zeroing.
#define BN 32
#define BK 32

__global__ void __launch_bounds__(256) gemm_nt(
    const float* __restrict__ A0, const float* __restrict__ W0,
    const float* __restrict__ A1, const float* __restrict__ W1,
    float* __restrict__ part)
{
    const int which = blockIdx.y >> 3;
    const float* __restrict__ A = which ? A1 : A0;
    const float* __restrict__ W = which ? W1 : W0;
    const int k0  = (blockIdx.y & (KS - 1)) * KCHUNK;
    const int dn0 = blockIdx.x * BN;
    float* __restrict__ out = part + (size_t)blockIdx.y * B * D;

    __shared__ float As[64][BK + 1];
    __shared__ float Ws[BN][BK + 1];

    const int tid = threadIdx.x;
    const int tx = tid & 15;   // d pair
    const int ty = tid >> 4;   // b quad
    float acc[4][2] = {};

    for (int bk = 0; bk < KCHUNK; bk += BK) {
        #pragma unroll
        for (int r = 0; r < 2; r++) {
            int idx = tid + r * 256;
            int bb = idx >> 3, kk4 = idx & 7;
            float4 v = *reinterpret_cast<const float4*>(A + bb * D + k0 + bk + kk4 * 4);
            As[bb][kk4 * 4 + 0] = v.x; As[bb][kk4 * 4 + 1] = v.y;
            As[bb][kk4 * 4 + 2] = v.z; As[bb][kk4 * 4 + 3] = v.w;
        }
        {
            int dd = tid >> 3, kk4 = tid & 7;
            float4 v = *reinterpret_cast<const float4*>(W + (size_t)(dn0 + dd) * D + k0 + bk + kk4 * 4);
            Ws[dd][kk4 * 4 + 0] = v.x; Ws[dd][kk4 * 4 + 1] = v.y;
            Ws[dd][kk4 * 4 + 2] = v.z; Ws[dd][kk4 * 4 + 3] = v.w;
        }
        __syncthreads();
        #pragma unroll
        for (int kk = 0; kk < BK; kk++) {
            float w0 = Ws[tx * 2][kk];
            float w1 = Ws[tx * 2 + 1][kk];
            #pragma unroll
            for (int i = 0; i < 4; i++) {
                float a = As[ty * 4 + i][kk];
                acc[i][0] = fmaf(a, w0, acc[i][0]);
                acc[i][1] = fmaf(a, w1, acc[i][1]);
            }
        }
        __syncthreads();
    }
    #pragma unroll
    for (int i = 0; i < 4; i++) {
        int b = ty * 4 + i;
        out[b * D + dn0 + tx * 2 + 0] = acc[i][0];
        out[b * D + dn0 + tx * 2 + 1] = acc[i][1];
    }
}

// ---------------- flash pass over context (the 1 GiB read) -----------------
// grid = (NSPLIT, B) = 512 CTAs, 256 threads, occ 4.
// Thread t owns output columns [4t, 4t+4). q-slice is reduced from the 8
// split-K partials once at start (amortized). Context tile is TRANSIENT in
// registers: loaded for the dot, discarded, re-loaded for the accumulate
// (second read hits L1: 32KB/CTA x 4 CTAs = 128KB < 228KB L1).
__global__ void __launch_bounds__(256, 4) attn_flash(
    const float* __restrict__ ctx, const int* __restrict__ mask)
{
    const int split = blockIdx.x;
    const int b     = blockIdx.y;
    const int tid   = threadIdx.x;
    const int lane  = tid & 31;
    const int wid   = tid >> 5;

    __shared__ float sh_red[2][8][8];    // [parity][row][warp]

    // reduce q-projection split-K partials for my 4 columns
    float4 qr = make_float4(0.f, 0.f, 0.f, 0.f);
    #pragma unroll
    for (int k = 0; k < KS; k++) {
        float4 v = *reinterpret_cast<const float4*>(g_qpart + (size_t)k * B * D + b * D + tid * 4);
        qr.x += v.x; qr.y += v.y; qr.z += v.z; qr.w += v.w;
    }

    float acc0 = 0.f, acc1 = 0.f, acc2 = 0.f, acc3 = 0.f;
    float m_run = -1e30f, l_run = 0.f;

    const float* __restrict__ cbase = ctx + (size_t)b * S * D + (size_t)split * SPS * D + tid * 4;
    const int*   __restrict__ mbase = mask + b * S + split * SPS;
    const int    sgbase = b * S + split * SPS;

    const bool h16 = (lane & 16) != 0;
    const bool h8  = (lane & 8)  != 0;
    const bool h4  = (lane & 4)  != 0;
    const int  myrow = lane & 7;

    for (int t = 0; t < NTILE; t++) {
        const int s0 = t * TILE;
        const float* tb = cbase + (size_t)s0 * D;
        const int par = t & 1;

        // ---- dot pass: f transient ----
        float p[TILE];
        #pragma unroll
        for (int j = 0; j < TILE; j++) {
            float4 f = *reinterpret_cast<const float4*>(tb + (size_t)j * D);
            p[j] = fmaf(f.x, qr.x, fmaf(f.y, qr.y, fmaf(f.z, qr.z, f.w * qr.w)));
        }

        // ---- butterfly fold: 8 rows x 32 lanes -> row (lane>>2) ----
        #pragma unroll
        for (int j = 0; j < 4; j++) {
            float send = h16 ? p[j] : p[j + 4];
            float recv = __shfl_xor_sync(0xffffffffu, send, 16);
            p[j] = (h16 ? p[j + 4] : p[j]) + recv;
        }
        #pragma unroll
        for (int j = 0; j < 2; j++) {
            float send = h8 ? p[j] : p[j + 2];
            float recv = __shfl_xor_sync(0xffffffffu, send, 8);
            p[j] = (h8 ? p[j + 2] : p[j]) + recv;
        }
        float pr;
        {
            float send = h4 ? p[0] : p[1];
            float recv = __shfl_xor_sync(0xffffffffu, send, 4);
            pr = (h4 ? p[1] : p[0]) + recv;
        }
        pr += __shfl_xor_sync(0xffffffffu, pr, 2);
        pr += __shfl_xor_sync(0xffffffffu, pr, 1);
        if ((lane & 3) == 0) sh_red[par][lane >> 2][wid] = pr;

        __syncthreads();   // single barrier per tile (smem double-buffered)

        // ---- cross-warp combine (redundant per warp) + mask ----
        float v = 0.f;
        #pragma unroll
        for (int w = 0; w < 8; w++) v += sh_red[par][myrow][w];
        float a = (mbase[s0 + myrow] != 0) ? v : -1e30f;
        if (wid == 0 && lane < 8) g_scores[sgbase + s0 + lane] = a;

        float aj[TILE];
        #pragma unroll
        for (int j = 0; j < TILE; j++)
            aj[j] = __shfl_sync(0xffffffffu, a, j, 8);

        // ---- online softmax ----
        float new_m = m_run;
        #pragma unroll
        for (int j = 0; j < TILE; j++) new_m = fmaxf(new_m, aj[j]);
        float scale = __expf(m_run - new_m);
        float wj[TILE];
        float wsum = 0.f;
        #pragma unroll
        for (int j = 0; j < TILE; j++) {
            wj[j] = (aj[j] > -1e29f) ? __expf(aj[j] - new_m) : 0.f;
            wsum += wj[j];
        }
        m_run = new_m;
        l_run = fmaf(l_run, scale, wsum);
        acc0 *= scale; acc1 *= scale; acc2 *= scale; acc3 *= scale;

        // ---- weighted accumulate: re-load tile (L1 hit) ----
        #pragma unroll
        for (int j = 0; j < TILE; j++) {
            float4 f = *reinterpret_cast<const float4*>(tb + (size_t)j * D);
            acc0 = fmaf(wj[j], f.x, acc0);
            acc1 = fmaf(wj[j], f.y, acc1);
            acc2 = fmaf(wj[j], f.z, acc2);
            acc3 = fmaf(wj[j], f.w, acc3);
        }
    }

    if (tid == 0) {
        g_pm[b * NSPLIT + split] = m_run;
        g_pl[b * NSPLIT + split] = l_run;
    }
    float* pa = g_pacc + (size_t)(b * NSPLIT + split) * D + tid * 4;
    pa[0] = acc0; pa[1] = acc1; pa[2] = acc2; pa[3] = acc3;
}

// ---------------- combine splits, normalize attention, emit weight_context -
// grid (B, 8) x 128 threads: exactly one attention float4 per thread;
// wc handled by threads 0..31 (32 float4 = 128 cols per block).
__global__ void __launch_bounds__(128) combine_kernel(float* __restrict__ out_att,
                                                      float* __restrict__ out_wc)
{
    const int b = blockIdx.x;
    const int c = blockIdx.y;
    const int tid = threadIdx.x;

    float M = -1e30f;
    #pragma unroll
    for (int i = 0; i < NSPLIT; i++) M = fmaxf(M, g_pm[b * NSPLIT + i]);
    float fac[NSPLIT];
    float L = 0.f;
    #pragma unroll
    for (int i = 0; i < NSPLIT; i++) {
        fac[i] = __expf(g_pm[b * NSPLIT + i] - M);
        L = fmaf(g_pl[b * NSPLIT + i], fac[i], L);
    }
    const float invL = 1.f / L;

    // weight_context: 128 cols (32 float4) per block
    if (tid < 32) {
        const int d4 = c * 32 + tid;
        const float4* pacc4 = reinterpret_cast<const float4*>(g_pacc) + (size_t)b * NSPLIT * (D / 4) + d4;
        float4 acc = make_float4(0.f, 0.f, 0.f, 0.f);
        #pragma unroll
        for (int i = 0; i < NSPLIT; i++) {
            float4 v = pacc4[(size_t)i * (D / 4)];
            acc.x = fmaf(fac[i], v.x, acc.x);
            acc.y = fmaf(fac[i], v.y, acc.y);
            acc.z = fmaf(fac[i], v.z, acc.z);
            acc.w = fmaf(fac[i], v.w, acc.w);
        }
        float4 wc = make_float4(acc.x * invL, acc.y * invL, acc.z * invL, acc.w * invL);
        reinterpret_cast<float4*>(g_wc)[b * (D / 4) + d4] = wc;
        reinterpret_cast<float4*>(out_wc)[b * (D / 4) + d4] = wc;
    }

    // attention: 512 scores (128 float4) per block, one per thread
    {
        const int s4 = c * 128 + tid;
        float4 sc = reinterpret_cast<const float4*>(g_scores)[b * (S / 4) + s4];
        float4 r = make_float4(__expf(sc.x - M) * invL, __expf(sc.y - M) * invL,
                               __expf(sc.z - M) * invL, __expf(sc.w - M) * invL);
        reinterpret_cast<float4*>(out_att)[b * (S / 4) + s4] = r;
    }
}

// ---------------- reduce output-GEMM partials + tanh ------------------------
__global__ void tanh_kernel(float* __restrict__ out) {
    int i = blockIdx.x * blockDim.x + threadIdx.x;   // float4 index, 16384 total
    float4 acc = make_float4(0.f, 0.f, 0.f, 0.f);
    #pragma unroll
    for (int k = 0; k < 2 * KS; k++) {
        float4 v = reinterpret_cast<const float4*>(g_linpart)[(size_t)k * (B * D / 4) + i];
        acc.x += v.x; acc.y += v.y; acc.z += v.z; acc.w += v.w;
    }
    float4 r = make_float4(tanhf(acc.x), tanhf(acc.y), tanhf(acc.z), tanhf(acc.w));
    reinterpret_cast<float4*>(out)[i] = r;
}

// ---------------- launcher --------------------------------------------------
extern "C" void kernel_launch(void* const* d_in, const int* in_sizes, int n_in,
                              void* d_out, int out_size)
{
    const float* query     = (const float*)d_in[0];   // [B, D]
    const float* context   = (const float*)d_in[1];   // [B, S, D]
    const int*   ctx_mask  = (const int*)  d_in[2];   // [B, S]
    const float* W_align   = (const float*)d_in[3];   // [D, D]
    const float* W_context = (const float*)d_in[4];   // [D, D]
    const float* W_query   = (const float*)d_in[5];   // [D, D]

    float* out  = (float*)d_out;                      // [B, D]
    float* att  = out + B * D;                        // [B, S]
    float* owc  = att + B * S;                        // [B, D]

    // Device addresses of symbols passed as kernel arguments.
    float *pqpart = nullptr, *plinpart = nullptr, *pwc = nullptr;
    cudaGetSymbolAddress((void**)&pqpart,   g_qpart);
    cudaGetSymbolAddress((void**)&plinpart, g_linpart);
    cudaGetSymbolAddress((void**)&pwc,      g_wc);

    // 1. q partials = query @ W_align^T   (split-K x8, no atomics)
    gemm_nt<<<dim3(D / BN, KS), 256>>>(query, W_align, query, W_align, pqpart);

    // 2. flash pass over context (1 GiB, read once from DRAM); reduces q partials
    attn_flash<<<dim3(NSPLIT, B), 256>>>(context, ctx_mask);

    // 3. combine splits -> attention + weight_context
    combine_kernel<<<dim3(B, 8), 128>>>(att, owc);

    // 4. lin partials: wc @ W_context^T (splits 0-7) + query @ W_query^T (8-15)
    gemm_nt<<<dim3(D / BN, 2 * KS), 256>>>(pwc, W_context, query, W_query, plinpart);

    // 5. out = tanh(sum of 16 partials)
    tanh_kernel<<<64, 256>>>(out);
}

// round 6
// speedup vs baseline: 1.0095x; 1.0077x over previous
#include <cuda_runtime.h>
#include <cuda_bf16.h>
#include <math.h>

#define B 64
#define S 4096
#define D 1024
#define NSPLIT 8
#define SPS (S / NSPLIT)   // 512
#define TILE 8
#define NTILE (SPS / TILE) // 64

#define KS 8               // split-K for launch 1 (per operand)
#define LIN_SLOTS 24       // 16 (wc@Wc, split-K 16) + 8 (q@Wq, split-K 8)

// ---------------- scratch (device globals: no allocation allowed) ----------
__device__ float g_qpart[KS * B * D];            // 2 MB  q-projection partials
__device__ float g_scores[B * S];                // 1 MB  masked raw scores
__device__ float g_pm[B * NSPLIT];
__device__ float g_pl[B * NSPLIT];
__device__ float g_pacc[B * NSPLIT * D];         // 2 MB  per-split unnormalized acc
__device__ float g_wc[B * D];
__device__ float g_linpart[LIN_SLOTS * B * D];   // 6 MB  output-GEMM partials

// ---------------- register-tiled skinny GEMM: partials of A @ W^T ----------
// Block: 64 b x 64 d tile over a k-chunk. 256 threads, each owns 4b x 4d.
// smem is k-major so the inner loop is 2 x LDS.128 + 16 FFMA per k.
// which = blockIdx.y >> op_shift selects operand pair; slot = low bits.
#define GBN 64
#define GBK 32

__global__ void __launch_bounds__(256) gemm_nt(
    const float* __restrict__ A0, const float* __restrict__ W0, float* __restrict__ out0,
    const float* __restrict__ A1, const float* __restrict__ W1, float* __restrict__ out1,
    int op_shift, int kchunk)
{
    const int which = blockIdx.y >> op_shift;
    const int slot  = blockIdx.y & ((1 << op_shift) - 1);
    const float* __restrict__ A = which ? A1 : A0;
    const float* __restrict__ W = which ? W1 : W0;
    float* __restrict__ outp = (which ? out1 : out0) + (size_t)slot * B * D;
    const int k0  = slot * kchunk;
    const int dn0 = blockIdx.x * GBN;

    __shared__ float As[GBK][B];     // [k][b]
    __shared__ float Ws[GBK][GBN];   // [k][d]

    const int tid = threadIdx.x;
    const int tx = tid & 15;         // d quad
    const int ty = tid >> 4;         // b quad

    float acc[4][4] = {};

    for (int bk = 0; bk < kchunk; bk += GBK) {
        // load A tile 64b x 32k -> As[k][b]; 2 lanes per row (32B each)
        #pragma unroll
        for (int r = 0; r < 2; r++) {
            int idx  = tid + r * 256;          // 0..511
            int pair = idx & 1;
            int bb   = (idx >> 1) & 63;
            int kq   = idx >> 7;               // 0..3
            int kb   = kq * 8 + pair * 4;
            float4 v = *reinterpret_cast<const float4*>(A + (size_t)bb * D + k0 + bk + kb);
            As[kb + 0][bb] = v.x; As[kb + 1][bb] = v.y;
            As[kb + 2][bb] = v.z; As[kb + 3][bb] = v.w;
        }
        // load W tile 64d x 32k -> Ws[k][d]
        #pragma unroll
        for (int r = 0; r < 2; r++) {
            int idx  = tid + r * 256;
            int pair = idx & 1;
            int dd   = (idx >> 1) & 63;
            int kq   = idx >> 7;
            int kb   = kq * 8 + pair * 4;
            float4 v = *reinterpret_cast<const float4*>(W + (size_t)(dn0 + dd) * D + k0 + bk + kb);
            Ws[kb + 0][dd] = v.x; Ws[kb + 1][dd] = v.y;
            Ws[kb + 2][dd] = v.z; Ws[kb + 3][dd] = v.w;
        }
        __syncthreads();
        #pragma unroll
        for (int kk = 0; kk < GBK; kk++) {
            float4 a = *reinterpret_cast<const float4*>(&As[kk][ty * 4]);
            float4 w = *reinterpret_cast<const float4*>(&Ws[kk][tx * 4]);
            acc[0][0] = fmaf(a.x, w.x, acc[0][0]); acc[0][1] = fmaf(a.x, w.y, acc[0][1]);
            acc[0][2] = fmaf(a.x, w.z, acc[0][2]); acc[0][3] = fmaf(a.x, w.w, acc[0][3]);
            acc[1][0] = fmaf(a.y, w.x, acc[1][0]); acc[1][1] = fmaf(a.y, w.y, acc[1][1]);
            acc[1][2] = fmaf(a.y, w.z, acc[1][2]); acc[1][3] = fmaf(a.y, w.w, acc[1][3]);
            acc[2][0] = fmaf(a.z, w.x, acc[2][0]); acc[2][1] = fmaf(a.z, w.y, acc[2][1]);
            acc[2][2] = fmaf(a.z, w.z, acc[2][2]); acc[2][3] = fmaf(a.z, w.w, acc[2][3]);
            acc[3][0] = fmaf(a.w, w.x, acc[3][0]); acc[3][1] = fmaf(a.w, w.y, acc[3][1]);
            acc[3][2] = fmaf(a.w, w.z, acc[3][2]); acc[3][3] = fmaf(a.w, w.w, acc[3][3]);
        }
        __syncthreads();
    }
    #pragma unroll
    for (int bi = 0; bi < 4; bi++) {
        float4 r = make_float4(acc[bi][0], acc[bi][1], acc[bi][2], acc[bi][3]);
        *reinterpret_cast<float4*>(outp + (size_t)(ty * 4 + bi) * D + dn0 + tx * 4) = r;
    }
}

// ---------------- flash pass over context (the 1 GiB read) -----------------
__global__ void __launch_bounds__(256, 4) attn_flash(
    const float* __restrict__ ctx, const int* __restrict__ mask)
{
    const int split = blockIdx.x;
    const int b     = blockIdx.y;
    const int tid   = threadIdx.x;
    const int lane  = tid & 31;
    const int wid   = tid >> 5;

    __shared__ float sh_red[2][8][8];    // [parity][row][warp]

    // reduce q-projection split-K partials for my 4 columns
    float4 qr = make_float4(0.f, 0.f, 0.f, 0.f);
    #pragma unroll
    for (int k = 0; k < KS; k++) {
        float4 v = *reinterpret_cast<const float4*>(g_qpart + (size_t)k * B * D + b * D + tid * 4);
        qr.x += v.x; qr.y += v.y; qr.z += v.z; qr.w += v.w;
    }

    float acc0 = 0.f, acc1 = 0.f, acc2 = 0.f, acc3 = 0.f;
    float m_run = -1e30f, l_run = 0.f;

    const float* __restrict__ cbase = ctx + (size_t)b * S * D + (size_t)split * SPS * D + tid * 4;
    const int*   __restrict__ mbase = mask + b * S + split * SPS;
    const int    sgbase = b * S + split * SPS;

    const bool h16 = (lane & 16) != 0;
    const bool h8  = (lane & 8)  != 0;
    const bool h4  = (lane & 4)  != 0;
    const int  myrow = lane & 7;

    for (int t = 0; t < NTILE; t++) {
        const int s0 = t * TILE;
        const float* tb = cbase + (size_t)s0 * D;
        const int par = t & 1;

        // ---- dot pass: f transient ----
        float p[TILE];
        #pragma unroll
        for (int j = 0; j < TILE; j++) {
            float4 f = *reinterpret_cast<const float4*>(tb + (size_t)j * D);
            p[j] = fmaf(f.x, qr.x, fmaf(f.y, qr.y, fmaf(f.z, qr.z, f.w * qr.w)));
        }

        // ---- butterfly fold: 8 rows x 32 lanes -> row (lane>>2) ----
        #pragma unroll
        for (int j = 0; j < 4; j++) {
            float send = h16 ? p[j] : p[j + 4];
            float recv = __shfl_xor_sync(0xffffffffu, send, 16);
            p[j] = (h16 ? p[j + 4] : p[j]) + recv;
        }
        #pragma unroll
        for (int j = 0; j < 2; j++) {
            float send = h8 ? p[j] : p[j + 2];
            float recv = __shfl_xor_sync(0xffffffffu, send, 8);
            p[j] = (h8 ? p[j + 2] : p[j]) + recv;
        }
        float pr;
        {
            float send = h4 ? p[0] : p[1];
            float recv = __shfl_xor_sync(0xffffffffu, send, 4);
            pr = (h4 ? p[1] : p[0]) + recv;
        }
        pr += __shfl_xor_sync(0xffffffffu, pr, 2);
        pr += __shfl_xor_sync(0xffffffffu, pr, 1);
        if ((lane & 3) == 0) sh_red[par][lane >> 2][wid] = pr;

        __syncthreads();   // single barrier per tile (smem double-buffered)

        // ---- cross-warp combine (redundant per warp) + mask ----
        float v = 0.f;
        #pragma unroll
        for (int w = 0; w < 8; w++) v += sh_red[par][myrow][w];
        float a = (mbase[s0 + myrow] != 0) ? v : -1e30f;
        if (wid == 0 && lane < 8) g_scores[sgbase + s0 + lane] = a;

        float aj[TILE];
        #pragma unroll
        for (int j = 0; j < TILE; j++)
            aj[j] = __shfl_sync(0xffffffffu, a, j, 8);

        // ---- online softmax ----
        float new_m = m_run;
        #pragma unroll
        for (int j = 0; j < TILE; j++) new_m = fmaxf(new_m, aj[j]);
        float scale = __expf(m_run - new_m);
        float wj[TILE];
        float wsum = 0.f;
        #pragma unroll
        for (int j = 0; j < TILE; j++) {
            wj[j] = (aj[j] > -1e29f) ? __expf(aj[j] - new_m) : 0.f;
            wsum += wj[j];
        }
        m_run = new_m;
        l_run = fmaf(l_run, scale, wsum);
        acc0 *= scale; acc1 *= scale; acc2 *= scale; acc3 *= scale;

        // ---- weighted accumulate: re-load tile (L1 hit) ----
        #pragma unroll
        for (int j = 0; j < TILE; j++) {
            float4 f = *reinterpret_cast<const float4*>(tb + (size_t)j * D);
            acc0 = fmaf(wj[j], f.x, acc0);
            acc1 = fmaf(wj[j], f.y, acc1);
            acc2 = fmaf(wj[j], f.z, acc2);
            acc3 = fmaf(wj[j], f.w, acc3);
        }
    }

    if (tid == 0) {
        g_pm[b * NSPLIT + split] = m_run;
        g_pl[b * NSPLIT + split] = l_run;
    }
    float* pa = g_pacc + (size_t)(b * NSPLIT + split) * D + tid * 4;
    pa[0] = acc0; pa[1] = acc1; pa[2] = acc2; pa[3] = acc3;
}

// ---------------- combine splits, normalize attention, emit weight_context -
__global__ void __launch_bounds__(128) combine_kernel(float* __restrict__ out_att,
                                                      float* __restrict__ out_wc)
{
    const int b = blockIdx.x;
    const int c = blockIdx.y;
    const int tid = threadIdx.x;

    float M = -1e30f;
    #pragma unroll
    for (int i = 0; i < NSPLIT; i++) M = fmaxf(M, g_pm[b * NSPLIT + i]);
    float fac[NSPLIT];
    float L = 0.f;
    #pragma unroll
    for (int i = 0; i < NSPLIT; i++) {
        fac[i] = __expf(g_pm[b * NSPLIT + i] - M);
        L = fmaf(g_pl[b * NSPLIT + i], fac[i], L);
    }
    const float invL = 1.f / L;

    if (tid < 32) {
        const int d4 = c * 32 + tid;
        const float4* pacc4 = reinterpret_cast<const float4*>(g_pacc) + (size_t)b * NSPLIT * (D / 4) + d4;
        float4 acc = make_float4(0.f, 0.f, 0.f, 0.f);
        #pragma unroll
        for (int i = 0; i < NSPLIT; i++) {
            float4 v = pacc4[(size_t)i * (D / 4)];
            acc.x = fmaf(fac[i], v.x, acc.x);
            acc.y = fmaf(fac[i], v.y, acc.y);
            acc.z = fmaf(fac[i], v.z, acc.z);
            acc.w = fmaf(fac[i], v.w, acc.w);
        }
        float4 wc = make_float4(acc.x * invL, acc.y * invL, acc.z * invL, acc.w * invL);
        reinterpret_cast<float4*>(g_wc)[b * (D / 4) + d4] = wc;
        reinterpret_cast<float4*>(out_wc)[b * (D / 4) + d4] = wc;
    }

    {
        const int s4 = c * 128 + tid;
        float4 sc = reinterpret_cast<const float4*>(g_scores)[b * (S / 4) + s4];
        float4 r = make_float4(__expf(sc.x - M) * invL, __expf(sc.y - M) * invL,
                               __expf(sc.z - M) * invL, __expf(sc.w - M) * invL);
        reinterpret_cast<float4*>(out_att)[b * (S / 4) + s4] = r;
    }
}

// ---------------- reduce output-GEMM partials + tanh ------------------------
__global__ void tanh_kernel(float* __restrict__ out) {
    int i = blockIdx.x * blockDim.x + threadIdx.x;   // float4 index, 16384 total
    float4 acc = make_float4(0.f, 0.f, 0.f, 0.f);
    #pragma unroll
    for (int k = 0; k < LIN_SLOTS; k++) {
        float4 v = reinterpret_cast<const float4*>(g_linpart)[(size_t)k * (B * D / 4) + i];
        acc.x += v.x; acc.y += v.y; acc.z += v.z; acc.w += v.w;
    }
    float4 r = make_float4(tanhf(acc.x), tanhf(acc.y), tanhf(acc.z), tanhf(acc.w));
    reinterpret_cast<float4*>(out)[i] = r;
}

// ---------------- launcher --------------------------------------------------
extern "C" void kernel_launch(void* const* d_in, const int* in_sizes, int n_in,
                              void* d_out, int out_size)
{
    const float* query     = (const float*)d_in[0];   // [B, D]
    const float* context   = (const float*)d_in[1];   // [B, S, D]
    const int*   ctx_mask  = (const int*)  d_in[2];   // [B, S]
    const float* W_align   = (const float*)d_in[3];   // [D, D]
    const float* W_context = (const float*)d_in[4];   // [D, D]
    const float* W_query   = (const float*)d_in[5];   // [D, D]

    float* out  = (float*)d_out;                      // [B, D]
    float* att  = out + B * D;                        // [B, S]
    float* owc  = att + B * S;                        // [B, D]

    float *pqpart = nullptr, *plinpart = nullptr, *pwc = nullptr;
    cudaGetSymbolAddress((void**)&pqpart,   g_qpart);
    cudaGetSymbolAddress((void**)&plinpart, g_linpart);
    cudaGetSymbolAddress((void**)&pwc,      g_wc);

    // 1. q partials = query @ W_align^T (slots 0-7 of g_qpart)
    //    AND lin partials = query @ W_query^T (slots 16-23 of g_linpart)
    //    op_shift=3, kchunk=128, grid.y=16 (2 ops x 8 k-splits)
    gemm_nt<<<dim3(D / GBN, 2 * KS), 256>>>(query, W_align, pqpart,
                                            query, W_query, plinpart + (size_t)16 * B * D,
                                            3, 128);

    // 2. flash pass over context (1 GiB, read once); reduces q partials
    attn_flash<<<dim3(NSPLIT, B), 256>>>(context, ctx_mask);

    // 3. combine splits -> attention + weight_context
    combine_kernel<<<dim3(B, 8), 128>>>(att, owc);

    // 4. lin partials: wc @ W_context^T (slots 0-15, split-K 16, kchunk=64)
    gemm_nt<<<dim3(D / GBN, 16), 256>>>(pwc, W_context, plinpart,
                                        pwc, W_context, plinpart,   // unused op1
                                        4, 64);

    // 5. out = tanh(sum of 24 partial slots)
    tanh_kernel<<<64, 256>>>(out);
}

// round 7
// speedup vs baseline: 1.0222x; 1.0125x over previous
#include <cuda_runtime.h>
#include <cuda_bf16.h>
#include <math.h>

#define B 64
#define S 4096
#define D 1024
#define NSPLIT 8
#define SPS (S / NSPLIT)   // 512
#define TILE 8
#define NTILE (SPS / TILE) // 64

#define KS 8               // split-K for launch 1 (per operand)
#define LIN_SLOTS 24       // 16 (wc@Wc, split-K 16) + 8 (q@Wq, split-K 8)

// ---------------- scratch (device globals: no allocation allowed) ----------
__device__ float g_qpart[KS * B * D];            // 2 MB  q-projection partials
__device__ float g_scores[B * S];                // 1 MB  masked raw scores
__device__ float g_pm[B * NSPLIT];
__device__ float g_pl[B * NSPLIT];
__device__ float g_pacc[B * NSPLIT * D];         // 2 MB  per-split unnormalized acc
__device__ float g_wc[B * D];
__device__ float g_linpart[LIN_SLOTS * B * D];   // 6 MB  output-GEMM partials
__device__ int   g_cnt[B];                       // per-batch completion counters (reset by finisher)

// ---------------- register-tiled skinny GEMM: partials of A @ W^T ----------
// Block: 64 b x 64 d tile over a k-chunk. 256 threads, each owns 4b x 4d.
#define GBN 64
#define GBK 32

__global__ void __launch_bounds__(256) gemm_nt(
    const float* __restrict__ A0, const float* __restrict__ W0, float* __restrict__ out0,
    const float* __restrict__ A1, const float* __restrict__ W1, float* __restrict__ out1,
    int op_shift, int kchunk)
{
    const int which = blockIdx.y >> op_shift;
    const int slot  = blockIdx.y & ((1 << op_shift) - 1);
    const float* __restrict__ A = which ? A1 : A0;
    const float* __restrict__ W = which ? W1 : W0;
    float* __restrict__ outp = (which ? out1 : out0) + (size_t)slot * B * D;
    const int k0  = slot * kchunk;
    const int dn0 = blockIdx.x * GBN;

    __shared__ float As[GBK][B];     // [k][b]
    __shared__ float Ws[GBK][GBN];   // [k][d]

    const int tid = threadIdx.x;
    const int tx = tid & 15;         // d quad
    const int ty = tid >> 4;         // b quad

    float acc[4][4] = {};

    for (int bk = 0; bk < kchunk; bk += GBK) {
        #pragma unroll
        for (int r = 0; r < 2; r++) {
            int idx  = tid + r * 256;          // 0..511
            int pair = idx & 1;
            int bb   = (idx >> 1) & 63;
            int kq   = idx >> 7;               // 0..3
            int kb   = kq * 8 + pair * 4;
            float4 v = *reinterpret_cast<const float4*>(A + (size_t)bb * D + k0 + bk + kb);
            As[kb + 0][bb] = v.x; As[kb + 1][bb] = v.y;
            As[kb + 2][bb] = v.z; As[kb + 3][bb] = v.w;
        }
        #pragma unroll
        for (int r = 0; r < 2; r++) {
            int idx  = tid + r * 256;
            int pair = idx & 1;
            int dd   = (idx >> 1) & 63;
            int kq   = idx >> 7;
            int kb   = kq * 8 + pair * 4;
            float4 v = *reinterpret_cast<const float4*>(W + (size_t)(dn0 + dd) * D + k0 + bk + kb);
            Ws[kb + 0][dd] = v.x; Ws[kb + 1][dd] = v.y;
            Ws[kb + 2][dd] = v.z; Ws[kb + 3][dd] = v.w;
        }
        __syncthreads();
        #pragma unroll
        for (int kk = 0; kk < GBK; kk++) {
            float4 a = *reinterpret_cast<const float4*>(&As[kk][ty * 4]);
            float4 w = *reinterpret_cast<const float4*>(&Ws[kk][tx * 4]);
            acc[0][0] = fmaf(a.x, w.x, acc[0][0]); acc[0][1] = fmaf(a.x, w.y, acc[0][1]);
            acc[0][2] = fmaf(a.x, w.z, acc[0][2]); acc[0][3] = fmaf(a.x, w.w, acc[0][3]);
            acc[1][0] = fmaf(a.y, w.x, acc[1][0]); acc[1][1] = fmaf(a.y, w.y, acc[1][1]);
            acc[1][2] = fmaf(a.y, w.z, acc[1][2]); acc[1][3] = fmaf(a.y, w.w, acc[1][3]);
            acc[2][0] = fmaf(a.z, w.x, acc[2][0]); acc[2][1] = fmaf(a.z, w.y, acc[2][1]);
            acc[2][2] = fmaf(a.z, w.z, acc[2][2]); acc[2][3] = fmaf(a.z, w.w, acc[2][3]);
            acc[3][0] = fmaf(a.w, w.x, acc[3][0]); acc[3][1] = fmaf(a.w, w.y, acc[3][1]);
            acc[3][2] = fmaf(a.w, w.z, acc[3][2]); acc[3][3] = fmaf(a.w, w.w, acc[3][3]);
        }
        __syncthreads();
    }
    #pragma unroll
    for (int bi = 0; bi < 4; bi++) {
        float4 r = make_float4(acc[bi][0], acc[bi][1], acc[bi][2], acc[bi][3]);
        *reinterpret_cast<float4*>(outp + (size_t)(ty * 4 + bi) * D + dn0 + tx * 4) = r;
    }
}

// ---------------- flash pass over context + fused per-batch combine --------
// grid = (NSPLIT, B), 256 threads, occ 4. After writing split partials, each
// CTA fences + bumps g_cnt[b]; the LAST CTA for batch b performs the combine
// (M/L reduce, wc, attention normalize) so combine overlaps flash raggedness.
__global__ void __launch_bounds__(256, 4) attn_flash(
    const float* __restrict__ ctx, const int* __restrict__ mask,
    float* __restrict__ out_att, float* __restrict__ out_wc)
{
    const int split = blockIdx.x;
    const int b     = blockIdx.y;
    const int tid   = threadIdx.x;
    const int lane  = tid & 31;
    const int wid   = tid >> 5;

    __shared__ float sh_red[2][8][8];    // [parity][row][warp]
    __shared__ int   sh_last;

    // reduce q-projection split-K partials for my 4 columns
    float4 qr = make_float4(0.f, 0.f, 0.f, 0.f);
    #pragma unroll
    for (int k = 0; k < KS; k++) {
        float4 v = *reinterpret_cast<const float4*>(g_qpart + (size_t)k * B * D + b * D + tid * 4);
        qr.x += v.x; qr.y += v.y; qr.z += v.z; qr.w += v.w;
    }

    float acc0 = 0.f, acc1 = 0.f, acc2 = 0.f, acc3 = 0.f;
    float m_run = -1e30f, l_run = 0.f;

    const float* __restrict__ cbase = ctx + (size_t)b * S * D + (size_t)split * SPS * D + tid * 4;
    const int*   __restrict__ mbase = mask + b * S + split * SPS;
    const int    sgbase = b * S + split * SPS;

    const bool h16 = (lane & 16) != 0;
    const bool h8  = (lane & 8)  != 0;
    const bool h4  = (lane & 4)  != 0;
    const int  myrow = lane & 7;

    for (int t = 0; t < NTILE; t++) {
        const int s0 = t * TILE;
        const float* tb = cbase + (size_t)s0 * D;
        const int par = t & 1;

        // ---- dot pass: f transient ----
        float p[TILE];
        #pragma unroll
        for (int j = 0; j < TILE; j++) {
            float4 f = *reinterpret_cast<const float4*>(tb + (size_t)j * D);
            p[j] = fmaf(f.x, qr.x, fmaf(f.y, qr.y, fmaf(f.z, qr.z, f.w * qr.w)));
        }

        // ---- butterfly fold: 8 rows x 32 lanes -> row (lane>>2) ----
        #pragma unroll
        for (int j = 0; j < 4; j++) {
            float send = h16 ? p[j] : p[j + 4];
            float recv = __shfl_xor_sync(0xffffffffu, send, 16);
            p[j] = (h16 ? p[j + 4] : p[j]) + recv;
        }
        #pragma unroll
        for (int j = 0; j < 2; j++) {
            float send = h8 ? p[j] : p[j + 2];
            float recv = __shfl_xor_sync(0xffffffffu, send, 8);
            p[j] = (h8 ? p[j + 2] : p[j]) + recv;
        }
        float pr;
        {
            float send = h4 ? p[0] : p[1];
            float recv = __shfl_xor_sync(0xffffffffu, send, 4);
            pr = (h4 ? p[1] : p[0]) + recv;
        }
        pr += __shfl_xor_sync(0xffffffffu, pr, 2);
        pr += __shfl_xor_sync(0xffffffffu, pr, 1);
        if ((lane & 3) == 0) sh_red[par][lane >> 2][wid] = pr;

        __syncthreads();   // single barrier per tile (smem double-buffered)

        // ---- cross-warp combine (redundant per warp) + mask ----
        float v = 0.f;
        #pragma unroll
        for (int w = 0; w < 8; w++) v += sh_red[par][myrow][w];
        float a = (mbase[s0 + myrow] != 0) ? v : -1e30f;
        if (wid == 0 && lane < 8) g_scores[sgbase + s0 + lane] = a;

        float aj[TILE];
        #pragma unroll
        for (int j = 0; j < TILE; j++)
            aj[j] = __shfl_sync(0xffffffffu, a, j, 8);

        // ---- online softmax ----
        float new_m = m_run;
        #pragma unroll
        for (int j = 0; j < TILE; j++) new_m = fmaxf(new_m, aj[j]);
        float scale = __expf(m_run - new_m);
        float wj[TILE];
        float wsum = 0.f;
        #pragma unroll
        for (int j = 0; j < TILE; j++) {
            wj[j] = (aj[j] > -1e29f) ? __expf(aj[j] - new_m) : 0.f;
            wsum += wj[j];
        }
        m_run = new_m;
        l_run = fmaf(l_run, scale, wsum);
        acc0 *= scale; acc1 *= scale; acc2 *= scale; acc3 *= scale;

        // ---- weighted accumulate: re-load tile (L1 hit) ----
        #pragma unroll
        for (int j = 0; j < TILE; j++) {
            float4 f = *reinterpret_cast<const float4*>(tb + (size_t)j * D);
            acc0 = fmaf(wj[j], f.x, acc0);
            acc1 = fmaf(wj[j], f.y, acc1);
            acc2 = fmaf(wj[j], f.z, acc2);
            acc3 = fmaf(wj[j], f.w, acc3);
        }
    }

    // ---- publish split partials ----
    if (tid == 0) {
        g_pm[b * NSPLIT + split] = m_run;
        g_pl[b * NSPLIT + split] = l_run;
    }
    float* pa = g_pacc + (size_t)(b * NSPLIT + split) * D + tid * 4;
    pa[0] = acc0; pa[1] = acc1; pa[2] = acc2; pa[3] = acc3;

    // ---- last-CTA-per-batch performs the combine ----
    __threadfence();                         // release partials
    __syncthreads();                         // all threads' stores done before count
    if (tid == 0) {
        int prev = atomicAdd(&g_cnt[b], 1);
        sh_last = (prev == NSPLIT - 1);
    }
    __syncthreads();
    if (!sh_last) return;
    // acquire: count==NSPLIT observed via atomic after writers' release fences

    if (tid == 0) g_cnt[b] = 0;              // reset for next graph replay

    float M = -1e30f;
    #pragma unroll
    for (int i = 0; i < NSPLIT; i++) M = fmaxf(M, g_pm[b * NSPLIT + i]);
    float fac[NSPLIT];
    float L = 0.f;
    #pragma unroll
    for (int i = 0; i < NSPLIT; i++) {
        fac[i] = __expf(g_pm[b * NSPLIT + i] - M);
        L = fmaf(g_pl[b * NSPLIT + i], fac[i], L);
    }
    const float invL = 1.f / L;

    // weight_context: 1024 cols = 256 float4, one per thread
    {
        const float4* pacc4 = reinterpret_cast<const float4*>(g_pacc) + (size_t)b * NSPLIT * (D / 4) + tid;
        float4 acc = make_float4(0.f, 0.f, 0.f, 0.f);
        #pragma unroll
        for (int i = 0; i < NSPLIT; i++) {
            float4 v = pacc4[(size_t)i * (D / 4)];
            acc.x = fmaf(fac[i], v.x, acc.x);
            acc.y = fmaf(fac[i], v.y, acc.y);
            acc.z = fmaf(fac[i], v.z, acc.z);
            acc.w = fmaf(fac[i], v.w, acc.w);
        }
        float4 wc = make_float4(acc.x * invL, acc.y * invL, acc.z * invL, acc.w * invL);
        reinterpret_cast<float4*>(g_wc)[b * (D / 4) + tid] = wc;
        reinterpret_cast<float4*>(out_wc)[b * (D / 4) + tid] = wc;
    }

    // attention: 4096 scores = 1024 float4, 4 per thread
    #pragma unroll
    for (int r = 0; r < 4; r++) {
        const int s4 = r * 256 + tid;
        float4 sc = reinterpret_cast<const float4*>(g_scores)[b * (S / 4) + s4];
        float4 rr = make_float4(__expf(sc.x - M) * invL, __expf(sc.y - M) * invL,
                                __expf(sc.z - M) * invL, __expf(sc.w - M) * invL);
        reinterpret_cast<float4*>(out_att)[b * (S / 4) + s4] = rr;
    }
}

// ---------------- reduce output-GEMM partials + tanh ------------------------
__global__ void tanh_kernel(float* __restrict__ out) {
    int i = blockIdx.x * blockDim.x + threadIdx.x;   // float4 index, 16384 total
    float4 acc = make_float4(0.f, 0.f, 0.f, 0.f);
    #pragma unroll
    for (int k = 0; k < LIN_SLOTS; k++) {
        float4 v = reinterpret_cast<const float4*>(g_linpart)[(size_t)k * (B * D / 4) + i];
        acc.x += v.x; acc.y += v.y; acc.z += v.z; acc.w += v.w;
    }
    float4 r = make_float4(tanhf(acc.x), tanhf(acc.y), tanhf(acc.z), tanhf(acc.w));
    reinterpret_cast<float4*>(out)[i] = r;
}

// ---------------- launcher --------------------------------------------------
extern "C" void kernel_launch(void* const* d_in, const int* in_sizes, int n_in,
                              void* d_out, int out_size)
{
    const float* query     = (const float*)d_in[0];   // [B, D]
    const float* context   = (const float*)d_in[1];   // [B, S, D]
    const int*   ctx_mask  = (const int*)  d_in[2];   // [B, S]
    const float* W_align   = (const float*)d_in[3];   // [D, D]
    const float* W_context = (const float*)d_in[4];   // [D, D]
    const float* W_query   = (const float*)d_in[5];   // [D, D]

    float* out  = (float*)d_out;                      // [B, D]
    float* att  = out + B * D;                        // [B, S]
    float* owc  = att + B * S;                        // [B, D]

    float *pqpart = nullptr, *plinpart = nullptr, *pwc = nullptr;
    cudaGetSymbolAddress((void**)&pqpart,   g_qpart);
    cudaGetSymbolAddress((void**)&plinpart, g_linpart);
    cudaGetSymbolAddress((void**)&pwc,      g_wc);

    // 1. q partials = query @ W_align^T (slots 0-7 of g_qpart)
    //    AND lin partials = query @ W_query^T (slots 16-23 of g_linpart)
    gemm_nt<<<dim3(D / GBN, 2 * KS), 256>>>(query, W_align, pqpart,
                                            query, W_query, plinpart + (size_t)16 * B * D,
                                            3, 128);

    // 2. flash pass over context (1 GiB, read once) + fused per-batch combine
    attn_flash<<<dim3(NSPLIT, B), 256>>>(context, ctx_mask, att, owc);

    // 3. lin partials: wc @ W_context^T (slots 0-15, split-K 16, kchunk=64)
    gemm_nt<<<dim3(D / GBN, 16), 256>>>(pwc, W_context, plinpart,
                                        pwc, W_context, plinpart,   // unused op1
                                        4, 64);

    // 4. out = tanh(sum of 24 partial slots)
    tanh_kernel<<<64, 256>>>(out);
}